// round 2
// baseline (speedup 1.0000x reference)
#include <cuda_runtime.h>
#include <cuda_bf16.h>

// ChamferDist: B=8, N=M=4096, 3D points.
// complete = mean_b mean_n min_m ||tar[b,n]-src[b,m]||
// accuracy = mean_b mean_m min_n ||tar[b,n]-src[b,m]||
// chamfer  = 0.5*(complete+accuracy)
// Output: [accuracy, complete, chamfer].
//
// Math trick: d^2 = |q|^2 + (|s|^2 - 2 q.s). Per pair we compute only
// (|s|^2 - 2 q.s) via a 3-FFMA2 packed chain (2 query points/instr),
// min-reduce, and add |q|^2 once per query point at the end.

#define NB   8
#define NP   4096
#define NDIR 2
#define T    256            // threads per block
#define R    8              // query points per thread (4 packed pairs)
#define TILE_P (T * R)      // 2048 query points per block
#define PT   (NP / TILE_P)  // 2 query tiles per (dir,batch)
#define S    16             // reference chunks
#define CHUNK (NP / S)      // 256 reference points per chunk

#define F_INF __int_as_float(0x7F800000)

// Scratch: per-point min squared distance + per-(dir,batch) sums.
__device__ float g_minsq[NDIR * NB * NP];
__device__ float g_bsum[NDIR * NB];

// ---- packed f32x2 helpers (Blackwell FFMA2 path) ----
__device__ __forceinline__ unsigned long long pack2(float lo, float hi) {
    unsigned long long r;
    asm("mov.b64 %0, {%1, %2};" : "=l"(r) : "f"(lo), "f"(hi));
    return r;
}
__device__ __forceinline__ unsigned long long fma2(unsigned long long a,
                                                   unsigned long long b,
                                                   unsigned long long c) {
    unsigned long long d;
    asm("fma.rn.f32x2 %0, %1, %2, %3;" : "=l"(d) : "l"(a), "l"(b), "l"(c));
    return d;
}
__device__ __forceinline__ void unpack2(unsigned long long v, float& lo, float& hi) {
    asm("mov.b64 {%0, %1}, %2;" : "=f"(lo), "=f"(hi) : "l"(v));
}

__global__ void cd_init() {
    int i = blockIdx.x * blockDim.x + threadIdx.x;
    if (i < NDIR * NB * NP) g_minsq[i] = F_INF;
}

// dir 0: queries = tar, references = src  -> complete
// dir 1: queries = src, references = tar  -> accuracy
__global__ __launch_bounds__(T) void cd_main(const float* __restrict__ tar,
                                             const float* __restrict__ src) {
    // Reference chunk, pre-duplicated for packed math:
    //   spA[j] = (-2x, -2x, -2y, -2y)   spB[j] = (-2z, -2z, |s|^2, |s|^2)
    __shared__ float4 spA[CHUNK];
    __shared__ float4 spB[CHUNK];

    int bid   = blockIdx.x;
    int chunk = bid % S;
    int ptile = (bid / S) % PT;
    int batch = (bid / (S * PT)) % NB;
    int dir   = bid / (S * PT * NB);

    const float* Q  = dir ? src : tar;
    const float* Rf = dir ? tar : src;

    const float* rbase = Rf + (size_t)(batch * NP + chunk * CHUNK) * 3;
    for (int i = threadIdx.x; i < CHUNK; i += T) {
        float x = rbase[i * 3 + 0];
        float y = rbase[i * 3 + 1];
        float z = rbase[i * 3 + 2];
        float nx = -2.0f * x, ny = -2.0f * y, nz = -2.0f * z;
        float n2 = fmaf(x, x, fmaf(y, y, z * z));
        spA[i] = make_float4(nx, nx, ny, ny);
        spB[i] = make_float4(nz, nz, n2, n2);
    }

    // Load R query points; pack coords pairwise into f32x2 registers.
    float qn[R], m[R];
    unsigned long long qx2[R / 2], qy2[R / 2], qz2[R / 2];
    {
        float qx[R], qy[R], qz[R];
        const float* qbase = Q + (size_t)(batch * NP + ptile * TILE_P) * 3;
#pragma unroll
        for (int k = 0; k < R; ++k) {
            int p = threadIdx.x + k * T;
            float x = qbase[p * 3 + 0];
            float y = qbase[p * 3 + 1];
            float z = qbase[p * 3 + 2];
            qx[k] = x; qy[k] = y; qz[k] = z;
            qn[k] = fmaf(x, x, fmaf(y, y, z * z));
            m[k]  = F_INF;
        }
#pragma unroll
        for (int k = 0; k < R / 2; ++k) {
            qx2[k] = pack2(qx[2 * k], qx[2 * k + 1]);
            qy2[k] = pack2(qy[2 * k], qy[2 * k + 1]);
            qz2[k] = pack2(qz[2 * k], qz[2 * k + 1]);
        }
    }
    __syncthreads();

    const unsigned long long* sA = (const unsigned long long*)spA;
    const unsigned long long* sB = (const unsigned long long*)spB;

#pragma unroll 2
    for (int j = 0; j < CHUNK; ++j) {
        // Two LDS.128 per j: (sxx, syy) and (szz, sww), broadcast, conflict-free.
        unsigned long long sxx = sA[2 * j], syy = sA[2 * j + 1];
        unsigned long long szz = sB[2 * j], sww = sB[2 * j + 1];
#pragma unroll
        for (int k = 0; k < R / 2; ++k) {
            unsigned long long d = fma2(qx2[k], sxx, fma2(qy2[k], syy, fma2(qz2[k], szz, sww)));
            float d0, d1;
            unpack2(d, d0, d1);
            m[2 * k]     = fminf(m[2 * k], d0);
            m[2 * k + 1] = fminf(m[2 * k + 1], d1);
        }
    }

    // Merge partial mins across chunks. Values clamped >= 0, so int-bit
    // atomicMin preserves float ordering.
    int base = (dir * NB + batch) * NP + ptile * TILE_P;
#pragma unroll
    for (int k = 0; k < R; ++k) {
        float v = fmaxf(m[k] + qn[k], 0.0f);
        atomicMin((int*)&g_minsq[base + threadIdx.x + k * T], __float_as_int(v));
    }
}

// One block per (dir,batch): sum of sqrt(minsq) over the 4096 points.
__global__ __launch_bounds__(256) void cd_reduce() {
    __shared__ float red[256];
    int idx = blockIdx.x;  // dir*NB + batch
    const float* p = g_minsq + (size_t)idx * NP;
    float s = 0.0f;
    for (int i = threadIdx.x; i < NP; i += 256) s += sqrtf(p[i]);
    red[threadIdx.x] = s;
    __syncthreads();
    for (int off = 128; off > 0; off >>= 1) {
        if (threadIdx.x < off) red[threadIdx.x] += red[threadIdx.x + off];
        __syncthreads();
    }
    if (threadIdx.x == 0) g_bsum[idx] = red[0];
}

__global__ void cd_final(float* __restrict__ out) {
    float comp = 0.0f, acc = 0.0f;
    for (int b = 0; b < NB; ++b) {
        comp += g_bsum[b];       // dir 0: tar queries -> complete
        acc  += g_bsum[NB + b];  // dir 1: src queries -> accuracy
    }
    comp *= (1.0f / (float)(NB * NP));
    acc  *= (1.0f / (float)(NB * NP));
    out[0] = acc;
    out[1] = comp;
    out[2] = 0.5f * (acc + comp);
}

extern "C" void kernel_launch(void* const* d_in, const int* in_sizes, int n_in,
                              void* d_out, int out_size) {
    const float* tar = (const float*)d_in[0];
    const float* src = (const float*)d_in[1];
    float* out = (float*)d_out;

    cd_init<<<(NDIR * NB * NP + 255) / 256, 256>>>();
    cd_main<<<NDIR * NB * PT * S, T>>>(tar, src);
    cd_reduce<<<NDIR * NB, 256>>>();
    cd_final<<<1, 1>>>(out);
}